// round 14
// baseline (speedup 1.0000x reference)
#include <cuda_runtime.h>
#include <cuda_bf16.h>
#include <math.h>
#include <stdint.h>

#define B_     2
#define S_     2048
#define DM     1024
#define H_     16
#define DK     64
#define INNER_ 1024
#define NREL   4095

// ---------------- device scratch (pre-split bf16 hi/lo, packed x2) ----------
__device__ unsigned g_xH[4096 * 512], g_xL[4096 * 512];      // X  [row][kpair]
__device__ unsigned g_wH[4 * 512 * 1024], g_wL[4 * 512 * 1024]; // [z][kpair][n]
__device__ unsigned g_qH[2 * 16 * 2048 * 32], g_qL[2 * 16 * 2048 * 32]; // [b,h,s,dpair]
__device__ unsigned g_kH[2 * 16 * 2048 * 32], g_kL[2 * 16 * 2048 * 32];
__device__ float    g_v [2 * 16 * 2048 * 64];                // fp32 [b,h,s,d]
__device__ unsigned g_vH[2 * 16 * 1024 * 64], g_vL[2 * 16 * 1024 * 64]; // [b,h,spair,d]
__device__ unsigned g_cH[4096 * 512], g_cL[4096 * 512];      // ctx [row][cpair]
__device__ float    g_bias[H_ * NREL];

// ---------------- bf16 helpers ----------------
__device__ __forceinline__ unsigned packbf(float x0, float x1) {
    __nv_bfloat162 t = __floats2bfloat162_rn(x0, x1);   // low = x0
    return *reinterpret_cast<unsigned*>(&t);
}
__device__ __forceinline__ void split2(float x0, float x1,
                                       unsigned& h, unsigned& l) {
    float h0 = __bfloat162float(__float2bfloat16_rn(x0));
    float h1 = __bfloat162float(__float2bfloat16_rn(x1));
    h = packbf(h0, h1);
    l = packbf(x0 - h0, x1 - h1);
}
__device__ __forceinline__ void mma_bf16(float* c, unsigned a0, unsigned a1,
                                         unsigned a2, unsigned a3,
                                         unsigned b0, unsigned b1) {
    asm volatile(
        "mma.sync.aligned.m16n8k16.row.col.f32.bf16.bf16.f32 "
        "{%0,%1,%2,%3}, {%4,%5,%6,%7}, {%8,%9}, {%0,%1,%2,%3};\n"
        : "+f"(c[0]), "+f"(c[1]), "+f"(c[2]), "+f"(c[3])
        : "r"(a0), "r"(a1), "r"(a2), "r"(a3), "r"(b0), "r"(b1));
}
__device__ __forceinline__ void mma3(float* c, const unsigned* aH,
                                     const unsigned* aL, unsigned bH0,
                                     unsigned bH1, unsigned bL0, unsigned bL1) {
    mma_bf16(c, aH[0], aH[1], aH[2], aH[3], bH0, bH1);
    mma_bf16(c, aH[0], aH[1], aH[2], aH[3], bL0, bL1);
    mma_bf16(c, aL[0], aL[1], aL[2], aL[3], bH0, bH1);
}

// ---------------- relative position bias table ----------------
__global__ void bias_kernel(const float* __restrict__ table) {
    int idx = blockIdx.x * blockDim.x + threadIdx.x;
    if (idx >= H_ * NREL) return;
    int h   = idx / NREL;
    int rel = (idx % NREL) - 2047;
    int rb  = (rel > 0) ? 16 : 0;
    int r   = abs(rel);
    int v;
    if (r < 8) {
        v = r;
    } else {
        float t = logf((float)r * 0.125f) / 2.7725887f * 8.0f;
        v = 8 + (int)t;
        v = min(v, 15);
    }
    g_bias[idx] = table[(rb + v) * H_ + h];
}

// ---------------- prep: split X and weights once ----------------
__global__ void prep_x(const float* __restrict__ X) {
    int idx = blockIdx.x * 256 + threadIdx.x;      // 4096*512
    int r = idx >> 9, p = idx & 511;
    float2 v = *(const float2*)(X + (size_t)r * 1024 + p * 2);
    unsigned h, l;
    split2(v.x, v.y, h, l);
    g_xH[idx] = h;
    g_xL[idx] = l;
}

__global__ void prep_w(const float* __restrict__ wq, const float* __restrict__ wk,
                       const float* __restrict__ wv, const float* __restrict__ wo) {
    int z = blockIdx.y;
    const float* W = (z == 0) ? wq : (z == 1) ? wk : (z == 2) ? wv : wo;
    int idx = blockIdx.x * 256 + threadIdx.x;      // 512*1024
    int p = idx >> 10, n = idx & 1023;
    float w0 = W[(size_t)(2 * p) * 1024 + n];
    float w1 = W[(size_t)(2 * p + 1) * 1024 + n];
    unsigned h, l;
    split2(w0, w1, h, l);
    g_wH[z * 524288 + idx] = h;
    g_wL[z * 524288 + idx] = l;
}

// pair V across adjacent sequence rows (k-dim of the PV matmul)
__global__ void v_pair() {
    int idx = blockIdx.x * 256 + threadIdx.x;      // 2*16*1024*64
    int d = idx & 63;
    int p = (idx >> 6) & 1023;
    int bh = idx >> 16;
    const float* vb = g_v + (size_t)bh * 131072 + (size_t)(2 * p) * 64 + d;
    unsigned h, l;
    split2(vb[0], vb[64], h, l);
    g_vH[idx] = h;
    g_vL[idx] = l;
}

// ---------------- 3xBF16 GEMM 128x128x32, pre-split operands ----------------
// mode 1: A = Xsplit, W = g_w[z]; q/k written pre-split, v fp32
// mode 0: A = ctxsplit, W = g_w[3]; fp32 to Copt
#define APITCH 20
#define BPITCH 136

__global__ __launch_bounds__(256) void gemm_pre(float* __restrict__ Copt,
                                                int mode) {
    __shared__ unsigned AsH[128 * APITCH], AsL[128 * APITCH];
    __shared__ unsigned BsH[16 * BPITCH], BsL[16 * BPITCH];

    int z = blockIdx.z;
    const unsigned* AH = (mode == 0) ? g_cH : g_xH;
    const unsigned* AL = (mode == 0) ? g_cL : g_xL;
    int wz = (mode == 0) ? 3 : z;
    const unsigned* WH = g_wH + wz * 524288;
    const unsigned* WL = g_wL + wz * 524288;

    int tid  = threadIdx.x;
    int warp = tid >> 5, lane = tid & 31;
    int g = lane >> 2, tig = lane & 3;
    int wm = (warp >> 2) * 64, wn = (warp & 3) * 32;
    int bx = blockIdx.x, by = blockIdx.y;

    int ar = tid >> 1, ah = tid & 1;
    int bp0 = tid >> 5, bcq = tid & 31;
    const unsigned* aHp = AH + (size_t)(by * 128 + ar) * 512 + ah * 8;
    const unsigned* aLp = AL + (size_t)(by * 128 + ar) * 512 + ah * 8;
    const unsigned* wHp = WH + bx * 128 + bcq * 4;
    const unsigned* wLp = WL + bx * 128 + bcq * 4;

    float acc[4][4][4];
#pragma unroll
    for (int mi = 0; mi < 4; mi++)
#pragma unroll
        for (int ni = 0; ni < 4; ni++)
#pragma unroll
            for (int c = 0; c < 4; c++) acc[mi][ni][c] = 0.0f;

    uint4 aH0, aH1, aL0, aL1, bH0, bH1, bL0, bL1;
    // prefetch tile 0
    aH0 = *(const uint4*)(aHp);
    aH1 = *(const uint4*)(aHp + 4);
    aL0 = *(const uint4*)(aLp);
    aL1 = *(const uint4*)(aLp + 4);
    bH0 = *(const uint4*)(wHp + (size_t)bp0 * 1024);
    bH1 = *(const uint4*)(wHp + (size_t)(bp0 + 8) * 1024);
    bL0 = *(const uint4*)(wLp + (size_t)bp0 * 1024);
    bL1 = *(const uint4*)(wLp + (size_t)(bp0 + 8) * 1024);

    for (int kt = 0; kt < 32; kt++) {
        // store prefetched tile
        *(uint4*)&AsH[ar * APITCH + ah * 8]     = aH0;
        *(uint4*)&AsH[ar * APITCH + ah * 8 + 4] = aH1;
        *(uint4*)&AsL[ar * APITCH + ah * 8]     = aL0;
        *(uint4*)&AsL[ar * APITCH + ah * 8 + 4] = aL1;
        *(uint4*)&BsH[bp0 * BPITCH + bcq * 4]       = bH0;
        *(uint4*)&BsH[(bp0 + 8) * BPITCH + bcq * 4] = bH1;
        *(uint4*)&BsL[bp0 * BPITCH + bcq * 4]       = bL0;
        *(uint4*)&BsL[(bp0 + 8) * BPITCH + bcq * 4] = bL1;
        __syncthreads();

        if (kt + 1 < 32) {
            int k0 = (kt + 1) * 16;
            aH0 = *(const uint4*)(aHp + k0);
            aH1 = *(const uint4*)(aHp + k0 + 4);
            aL0 = *(const uint4*)(aLp + k0);
            aL1 = *(const uint4*)(aLp + k0 + 4);
            bH0 = *(const uint4*)(wHp + (size_t)(k0 + bp0) * 1024);
            bH1 = *(const uint4*)(wHp + (size_t)(k0 + bp0 + 8) * 1024);
            bL0 = *(const uint4*)(wLp + (size_t)(k0 + bp0) * 1024);
            bL1 = *(const uint4*)(wLp + (size_t)(k0 + bp0 + 8) * 1024);
        }

        // compute: 2 k16 steps
#pragma unroll
        for (int ks = 0; ks < 2; ks++) {
            int kp = ks * 8;
            unsigned afH[4][4], afL[4][4], bfH[4][2], bfL[4][2];
#pragma unroll
            for (int mi = 0; mi < 4; mi++) {
                int r = wm + mi * 16 + g;
                afH[mi][0] = AsH[r * APITCH + kp + tig];
                afH[mi][1] = AsH[(r + 8) * APITCH + kp + tig];
                afH[mi][2] = AsH[r * APITCH + kp + tig + 4];
                afH[mi][3] = AsH[(r + 8) * APITCH + kp + tig + 4];
                afL[mi][0] = AsL[r * APITCH + kp + tig];
                afL[mi][1] = AsL[(r + 8) * APITCH + kp + tig];
                afL[mi][2] = AsL[r * APITCH + kp + tig + 4];
                afL[mi][3] = AsL[(r + 8) * APITCH + kp + tig + 4];
            }
#pragma unroll
            for (int ni = 0; ni < 4; ni++) {
                int c = wn + ni * 8 + g;
                bfH[ni][0] = BsH[(kp + tig) * BPITCH + c];
                bfH[ni][1] = BsH[(kp + tig + 4) * BPITCH + c];
                bfL[ni][0] = BsL[(kp + tig) * BPITCH + c];
                bfL[ni][1] = BsL[(kp + tig + 4) * BPITCH + c];
            }
#pragma unroll
            for (int mi = 0; mi < 4; mi++)
#pragma unroll
                for (int ni = 0; ni < 4; ni++)
                    mma3(acc[mi][ni], afH[mi], afL[mi], bfH[ni][0], bfH[ni][1],
                         bfL[ni][0], bfL[ni][1]);
        }
        __syncthreads();
    }

    // epilogue
    if (mode == 0) {
#pragma unroll
        for (int mi = 0; mi < 4; mi++)
#pragma unroll
            for (int ni = 0; ni < 4; ni++) {
                int r0 = by * 128 + wm + mi * 16 + g;
                int c0 = bx * 128 + wn + ni * 8 + tig * 2;
                *(float2*)(Copt + (size_t)r0 * 1024 + c0) =
                    make_float2(acc[mi][ni][0], acc[mi][ni][1]);
                *(float2*)(Copt + (size_t)(r0 + 8) * 1024 + c0) =
                    make_float2(acc[mi][ni][2], acc[mi][ni][3]);
            }
    } else if (z < 2) {
        unsigned* dH = (z == 0) ? g_qH : g_kH;
        unsigned* dL = (z == 0) ? g_qL : g_kL;
#pragma unroll
        for (int mi = 0; mi < 4; mi++)
#pragma unroll
            for (int ni = 0; ni < 4; ni++) {
                int r0 = by * 128 + wm + mi * 16 + g;
                int c0 = bx * 128 + wn + ni * 8 + tig * 2;
                int h = c0 >> 6, dp = (c0 & 63) >> 1;
                {
                    int b = r0 >> 11, s = r0 & 2047;
                    size_t idx = ((size_t)(b * H_ + h) * S_ + s) * 32 + dp;
                    unsigned hw, lw;
                    split2(acc[mi][ni][0], acc[mi][ni][1], hw, lw);
                    dH[idx] = hw;
                    dL[idx] = lw;
                }
                {
                    int r1 = r0 + 8;
                    int b = r1 >> 11, s = r1 & 2047;
                    size_t idx = ((size_t)(b * H_ + h) * S_ + s) * 32 + dp;
                    unsigned hw, lw;
                    split2(acc[mi][ni][2], acc[mi][ni][3], hw, lw);
                    dH[idx] = hw;
                    dL[idx] = lw;
                }
            }
    } else {
#pragma unroll
        for (int mi = 0; mi < 4; mi++)
#pragma unroll
            for (int ni = 0; ni < 4; ni++) {
                int r0 = by * 128 + wm + mi * 16 + g;
                int c0 = bx * 128 + wn + ni * 8 + tig * 2;
                int h = c0 >> 6, d = c0 & 63;
                {
                    int b = r0 >> 11, s = r0 & 2047;
                    *(float2*)(g_v + (size_t)((b * H_ + h) * S_ + s) * DK + d) =
                        make_float2(acc[mi][ni][0], acc[mi][ni][1]);
                }
                {
                    int r1 = r0 + 8;
                    int b = r1 >> 11, s = r1 & 2047;
                    *(float2*)(g_v + (size_t)((b * H_ + h) * S_ + s) * DK + d) =
                        make_float2(acc[mi][ni][2], acc[mi][ni][3]);
                }
            }
    }
}

// ------- 3xBF16 flash attention, 128x64 tiles, pre-split Q/K/V --------------
#define QP 36
#define KP 36
#define VP 72
#define PP 36
#define FLASH_SMEM ((2 * 128 * QP + 2 * 64 * KP + 2 * 32 * VP + \
                     2 * 128 * PP + 192) * 4)

__global__ __launch_bounds__(256) void flash_bf16x3() {
    extern __shared__ unsigned smu[];
    unsigned* QsH = smu;
    unsigned* QsL = QsH + 128 * QP;
    unsigned* KsH = QsL + 128 * QP;
    unsigned* KsL = KsH + 64 * KP;
    unsigned* VsH = KsL + 64 * KP;
    unsigned* VsL = VsH + 32 * VP;
    unsigned* PsH = VsL + 32 * VP;
    unsigned* PsL = PsH + 128 * PP;
    float* sB = (float*)(PsL + 128 * PP);

    int qb = blockIdx.x, h = blockIdx.y, b = blockIdx.z;
    int tid  = threadIdx.x;
    int warp = tid >> 5, lane = tid & 31;
    int g = lane >> 2, tig = lane & 3;

    const unsigned* qHb = g_qH + ((size_t)(b * H_ + h) * S_ + qb * 128) * 32;
    const unsigned* qLb = g_qL + ((size_t)(b * H_ + h) * S_ + qb * 128) * 32;
    const unsigned* kHb = g_kH + (size_t)(b * H_ + h) * S_ * 32;
    const unsigned* kLb = g_kL + (size_t)(b * H_ + h) * S_ * 32;
    const unsigned* vHb = g_vH + (size_t)(b * H_ + h) * 1024 * 64;
    const unsigned* vLb = g_vL + (size_t)(b * H_ + h) * 1024 * 64;

    // load Q tile: straight copy of pre-split data
#pragma unroll
    for (int i = 0; i < 4; i++) {
        int ch = tid + i * 256;
        int r = ch >> 3, j = (ch & 7) * 4;
        *(uint4*)&QsH[r * QP + j] = *(const uint4*)(qHb + r * 32 + j);
        *(uint4*)&QsL[r * QP + j] = *(const uint4*)(qLb + r * 32 + j);
    }

    float oacc[8][4];
#pragma unroll
    for (int ni = 0; ni < 8; ni++)
#pragma unroll
        for (int c = 0; c < 4; c++) oacc[ni][c] = 0.0f;
    float m_i[2] = {-1e30f, -1e30f}, l_i[2] = {0.0f, 0.0f};

    for (int kb = 0; kb < S_ / 64; kb++) {
        // K tile: copy
#pragma unroll
        for (int i = 0; i < 2; i++) {
            int ch = tid + i * 256;
            int r = ch >> 3, j = (ch & 7) * 4;
            *(uint4*)&KsH[r * KP + j] = *(const uint4*)(kHb + (kb * 64 + r) * 32 + j);
            *(uint4*)&KsL[r * KP + j] = *(const uint4*)(kLb + (kb * 64 + r) * 32 + j);
        }
        // V tile: copy
#pragma unroll
        for (int i = 0; i < 2; i++) {
            int ch = tid + i * 256;
            int pl = ch >> 4, j = (ch & 15) * 4;
            *(uint4*)&VsH[pl * VP + j] = *(const uint4*)(vHb + (kb * 32 + pl) * 64 + j);
            *(uint4*)&VsL[pl * VP + j] = *(const uint4*)(vLb + (kb * 32 + pl) * 64 + j);
        }
        if (tid < 191)
            sB[tid] = g_bias[h * NREL + (kb * 64 - qb * 128) - 127 + 2047 + tid];
        __syncthreads();

        // S = Q @ K^T
        float sacc[8][4];
#pragma unroll
        for (int ni = 0; ni < 8; ni++)
#pragma unroll
            for (int c = 0; c < 4; c++) sacc[ni][c] = 0.0f;

#pragma unroll
        for (int ks = 0; ks < 4; ks++) {
            int kp = ks * 8;
            int rq = warp * 16 + g;
            unsigned aH[4], aL[4];
            aH[0] = QsH[rq * QP + kp + tig];
            aH[1] = QsH[(rq + 8) * QP + kp + tig];
            aH[2] = QsH[rq * QP + kp + tig + 4];
            aH[3] = QsH[(rq + 8) * QP + kp + tig + 4];
            aL[0] = QsL[rq * QP + kp + tig];
            aL[1] = QsL[(rq + 8) * QP + kp + tig];
            aL[2] = QsL[rq * QP + kp + tig + 4];
            aL[3] = QsL[(rq + 8) * QP + kp + tig + 4];
#pragma unroll
            for (int ni = 0; ni < 8; ni++) {
                int rk = ni * 8 + g;
                unsigned bH0 = KsH[rk * KP + kp + tig];
                unsigned bH1 = KsH[rk * KP + kp + tig + 4];
                unsigned bL0 = KsL[rk * KP + kp + tig];
                unsigned bL1 = KsL[rk * KP + kp + tig + 4];
                mma3(sacc[ni], aH, aL, bH0, bH1, bL0, bL1);
            }
        }

        // bias + online softmax
#pragma unroll
        for (int rh = 0; rh < 2; rh++) {
            int qr = warp * 16 + g + 8 * rh;
            float rm = -1e30f;
#pragma unroll
            for (int ni = 0; ni < 8; ni++) {
                int kc = ni * 8 + tig * 2;
                sacc[ni][2 * rh]     += sB[kc - qr + 127];
                sacc[ni][2 * rh + 1] += sB[kc + 1 - qr + 127];
                rm = fmaxf(rm, fmaxf(sacc[ni][2 * rh], sacc[ni][2 * rh + 1]));
            }
            rm = fmaxf(rm, __shfl_xor_sync(0xffffffffu, rm, 1));
            rm = fmaxf(rm, __shfl_xor_sync(0xffffffffu, rm, 2));
            float mn   = fmaxf(m_i[rh], rm);
            float corr = __expf(m_i[rh] - mn);
            float rs = 0.0f;
#pragma unroll
            for (int ni = 0; ni < 8; ni++) {
                float p0 = __expf(sacc[ni][2 * rh] - mn);
                float p1 = __expf(sacc[ni][2 * rh + 1] - mn);
                rs += p0 + p1;
                unsigned ph, pl;
                split2(p0, p1, ph, pl);
                PsH[qr * PP + ni * 4 + tig] = ph;
                PsL[qr * PP + ni * 4 + tig] = pl;
                oacc[ni][2 * rh]     *= corr;
                oacc[ni][2 * rh + 1] *= corr;
            }
            rs += __shfl_xor_sync(0xffffffffu, rs, 1);
            rs += __shfl_xor_sync(0xffffffffu, rs, 2);
            l_i[rh] = l_i[rh] * corr + rs;
            m_i[rh] = mn;
        }
        __syncwarp();   // P rows are warp-private

        // O += P @ V
#pragma unroll
        for (int ks = 0; ks < 4; ks++) {
            int kp = ks * 8;
            int pr = warp * 16 + g;
            unsigned aH[4], aL[4];
            aH[0] = PsH[pr * PP + kp + tig];
            aH[1] = PsH[(pr + 8) * PP + kp + tig];
            aH[2] = PsH[pr * PP + kp + tig + 4];
            aH[3] = PsH[(pr + 8) * PP + kp + tig + 4];
            aL[0] = PsL[pr * PP + kp + tig];
            aL[1] = PsL[(pr + 8) * PP + kp + tig];
            aL[2] = PsL[pr * PP + kp + tig + 4];
            aL[3] = PsL[(pr + 8) * PP + kp + tig + 4];
#pragma unroll
            for (int ni = 0; ni < 8; ni++) {
                int d = ni * 8 + g;
                unsigned bH0 = VsH[(kp + tig) * VP + d];
                unsigned bH1 = VsH[(kp + tig + 4) * VP + d];
                unsigned bL0 = VsL[(kp + tig) * VP + d];
                unsigned bL1 = VsL[(kp + tig + 4) * VP + d];
                mma3(oacc[ni], aH, aL, bH0, bH1, bL0, bL1);
            }
        }
        __syncthreads();
    }

    // normalize + write ctx PRE-SPLIT for the wo GEMM
    float inv0 = 1.0f / l_i[0], inv1 = 1.0f / l_i[1];
#pragma unroll
    for (int ni = 0; ni < 8; ni++) {
        int q0 = qb * 128 + warp * 16 + g;
        int cp = h * 32 + ni * 4 + tig;
        {
            size_t idx = ((size_t)b * S_ + q0) * 512 + cp;
            unsigned hw, lw;
            split2(oacc[ni][0] * inv0, oacc[ni][1] * inv0, hw, lw);
            g_cH[idx] = hw;
            g_cL[idx] = lw;
        }
        {
            size_t idx = ((size_t)b * S_ + q0 + 8) * 512 + cp;
            unsigned hw, lw;
            split2(oacc[ni][2] * inv1, oacc[ni][3] * inv1, hw, lw);
            g_cH[idx] = hw;
            g_cL[idx] = lw;
        }
    }
}

// ---------------- launch ----------------
extern "C" void kernel_launch(void* const* d_in, const int* in_sizes, int n_in,
                              void* d_out, int out_size) {
    const float* X     = (const float*)d_in[0];
    const float* wq    = (const float*)d_in[1];
    const float* wk    = (const float*)d_in[2];
    const float* wv    = (const float*)d_in[3];
    const float* wo    = (const float*)d_in[4];
    const float* table = (const float*)d_in[5];
    float* out = (float*)d_out;

    cudaFuncSetAttribute(flash_bf16x3,
                         cudaFuncAttributeMaxDynamicSharedMemorySize, FLASH_SMEM);

    // 1. bias table + one-time splits
    bias_kernel<<<(H_ * NREL + 255) / 256, 256>>>(table);
    prep_x<<<4096 * 512 / 256, 256>>>(X);
    dim3 gw(512 * 1024 / 256, 4);
    prep_w<<<gw, 256>>>(wq, wk, wv, wo);

    // 2. fused Q/K/V projections
    dim3 gq(INNER_ / 128, (B_ * S_) / 128, 3);
    gemm_pre<<<gq, 256>>>(nullptr, 1);

    // 3. pair V rows
    v_pair<<<2 * 16 * 1024 * 64 / 256, 256>>>();

    // 4. flash attention
    dim3 ga(S_ / 128, H_, B_);
    flash_bf16x3<<<ga, 256, FLASH_SMEM>>>();

    // 5. output projection
    dim3 go(DM / 128, (B_ * S_) / 128, 1);
    gemm_pre<<<go, 256>>>(out, 0);
}

// round 15
// speedup vs baseline: 1.0331x; 1.0331x over previous
#include <cuda_runtime.h>
#include <cuda_bf16.h>
#include <math.h>
#include <stdint.h>

#define B_     2
#define S_     2048
#define DM     1024
#define H_     16
#define DK     64
#define INNER_ 1024
#define NREL   4095

// ---------------- device scratch ----------------
__device__ float    g_q[B_ * H_ * S_ * DK];      // fp32 [B,H,S,DK]
__device__ float    g_k[B_ * H_ * S_ * DK];
__device__ float    g_v[B_ * H_ * S_ * DK];
__device__ float    g_ctx[B_ * S_ * INNER_];     // fp32 [B,S,H*DK]
__device__ float    g_bias[H_ * NREL];
// pre-split packed-bf16x2 operands for the GEMMs
__device__ unsigned g_xH[4096 * 512], g_xL[4096 * 512];        // X  [row][kpair]
__device__ unsigned g_wH[4 * 512 * 1024], g_wL[4 * 512 * 1024]; // [z][kpair][n]
__device__ unsigned g_cH[4096 * 512], g_cL[4096 * 512];        // ctx [row][cpair]

// ---------------- bf16 helpers ----------------
__device__ __forceinline__ unsigned packbf(float x0, float x1) {
    __nv_bfloat162 t = __floats2bfloat162_rn(x0, x1);   // low = x0
    return *reinterpret_cast<unsigned*>(&t);
}
__device__ __forceinline__ void split2(float x0, float x1,
                                       unsigned& h, unsigned& l) {
    float h0 = __bfloat162float(__float2bfloat16_rn(x0));
    float h1 = __bfloat162float(__float2bfloat16_rn(x1));
    h = packbf(h0, h1);
    l = packbf(x0 - h0, x1 - h1);
}
__device__ __forceinline__ void mma_bf16(float* c, unsigned a0, unsigned a1,
                                         unsigned a2, unsigned a3,
                                         unsigned b0, unsigned b1) {
    asm volatile(
        "mma.sync.aligned.m16n8k16.row.col.f32.bf16.bf16.f32 "
        "{%0,%1,%2,%3}, {%4,%5,%6,%7}, {%8,%9}, {%0,%1,%2,%3};\n"
        : "+f"(c[0]), "+f"(c[1]), "+f"(c[2]), "+f"(c[3])
        : "r"(a0), "r"(a1), "r"(a2), "r"(a3), "r"(b0), "r"(b1));
}
__device__ __forceinline__ void mma3(float* c, const unsigned* aH,
                                     const unsigned* aL, unsigned bH0,
                                     unsigned bH1, unsigned bL0, unsigned bL1) {
    mma_bf16(c, aH[0], aH[1], aH[2], aH[3], bH0, bH1);
    mma_bf16(c, aH[0], aH[1], aH[2], aH[3], bL0, bL1);
    mma_bf16(c, aL[0], aL[1], aL[2], aL[3], bH0, bH1);
}

// ---------------- relative position bias table ----------------
__global__ void bias_kernel(const float* __restrict__ table) {
    int idx = blockIdx.x * blockDim.x + threadIdx.x;
    if (idx >= H_ * NREL) return;
    int h   = idx / NREL;
    int rel = (idx % NREL) - 2047;
    int rb  = (rel > 0) ? 16 : 0;
    int r   = abs(rel);
    int v;
    if (r < 8) {
        v = r;
    } else {
        float t = logf((float)r * 0.125f) / 2.7725887f * 8.0f;
        v = 8 + (int)t;
        v = min(v, 15);
    }
    g_bias[idx] = table[(rb + v) * H_ + h];
}

// ---------------- prep: split X / weights / ctx once ----------------
__global__ void prep_x(const float* __restrict__ X) {
    int idx = blockIdx.x * 256 + threadIdx.x;      // 4096*512
    int r = idx >> 9, p = idx & 511;
    float2 v = *(const float2*)(X + (size_t)r * 1024 + p * 2);
    unsigned h, l;
    split2(v.x, v.y, h, l);
    g_xH[idx] = h;
    g_xL[idx] = l;
}
__global__ void prep_w(const float* __restrict__ wq, const float* __restrict__ wk,
                       const float* __restrict__ wv, const float* __restrict__ wo) {
    int z = blockIdx.y;
    const float* W = (z == 0) ? wq : (z == 1) ? wk : (z == 2) ? wv : wo;
    int idx = blockIdx.x * 256 + threadIdx.x;      // 512*1024
    int p = idx >> 10, n = idx & 1023;
    float w0 = W[(size_t)(2 * p) * 1024 + n];
    float w1 = W[(size_t)(2 * p + 1) * 1024 + n];
    unsigned h, l;
    split2(w0, w1, h, l);
    g_wH[z * 524288 + idx] = h;
    g_wL[z * 524288 + idx] = l;
}
__global__ void prep_c() {
    int idx = blockIdx.x * 256 + threadIdx.x;      // 4096*512
    int r = idx >> 9, p = idx & 511;
    float2 v = *(const float2*)(g_ctx + (size_t)r * 1024 + p * 2);
    unsigned h, l;
    split2(v.x, v.y, h, l);
    g_cH[idx] = h;
    g_cL[idx] = l;
}

// ------- 3xBF16 GEMM 128x64 tile, warp 32x32, 2 CTAs/SM ---------------------
// mode 1: A = Xsplit, W = g_w[z]; fp32 write to g_q/g_k/g_v ([B,H,S,DK])
// mode 0: A = ctxsplit, W = g_w[3]; fp32 row-major to Copt
#define APITCH 20    // 16 kpairs + 4 pad
#define BPITCH 72    // 64 cols + 8 pad

__global__ __launch_bounds__(256, 2) void gemm_occ(float* __restrict__ Copt,
                                                   int mode) {
    __shared__ unsigned AsH[128 * APITCH], AsL[128 * APITCH];
    __shared__ unsigned BsH[16 * BPITCH], BsL[16 * BPITCH];

    int z = blockIdx.z;
    const unsigned* AH = (mode == 0) ? g_cH : g_xH;
    const unsigned* AL = (mode == 0) ? g_cL : g_xL;
    int wz = (mode == 0) ? 3 : z;
    const unsigned* WH = g_wH + wz * 524288;
    const unsigned* WL = g_wL + wz * 524288;

    int tid  = threadIdx.x;
    int warp = tid >> 5, lane = tid & 31;
    int g = lane >> 2, tig = lane & 3;
    int wm = (warp >> 1) * 32;          // 4 warp-rows
    int wn = (warp & 1) * 32;           // 2 warp-cols
    int bx = blockIdx.x, by = blockIdx.y;

    // load coords: A thread covers row ar, 8 kpairs (half ahf); B: kpair bp, 4 cols
    int ar = tid >> 1, ahf = tid & 1;
    int bp = tid >> 4, bcq = tid & 15;
    const unsigned* aHp = AH + (size_t)(by * 128 + ar) * 512 + ahf * 8;
    const unsigned* aLp = AL + (size_t)(by * 128 + ar) * 512 + ahf * 8;
    const unsigned* wHp = WH + bx * 64 + bcq * 4;
    const unsigned* wLp = WL + bx * 64 + bcq * 4;

    float acc[2][4][4];
#pragma unroll
    for (int mi = 0; mi < 2; mi++)
#pragma unroll
        for (int ni = 0; ni < 4; ni++)
#pragma unroll
            for (int c = 0; c < 4; c++) acc[mi][ni][c] = 0.0f;

    uint4 aH0, aH1, aL0, aL1, bHr, bLr;
    // prefetch tile 0
    aH0 = *(const uint4*)(aHp);
    aH1 = *(const uint4*)(aHp + 4);
    aL0 = *(const uint4*)(aLp);
    aL1 = *(const uint4*)(aLp + 4);
    bHr = *(const uint4*)(wHp + (size_t)bp * 1024);
    bLr = *(const uint4*)(wLp + (size_t)bp * 1024);

    for (int kt = 0; kt < 32; kt++) {
        // store prefetched tile
        *(uint4*)&AsH[ar * APITCH + ahf * 8]     = aH0;
        *(uint4*)&AsH[ar * APITCH + ahf * 8 + 4] = aH1;
        *(uint4*)&AsL[ar * APITCH + ahf * 8]     = aL0;
        *(uint4*)&AsL[ar * APITCH + ahf * 8 + 4] = aL1;
        *(uint4*)&BsH[bp * BPITCH + bcq * 4] = bHr;
        *(uint4*)&BsL[bp * BPITCH + bcq * 4] = bLr;
        __syncthreads();

        if (kt + 1 < 32) {
            int k0 = (kt + 1) * 16;
            aH0 = *(const uint4*)(aHp + k0);
            aH1 = *(const uint4*)(aHp + k0 + 4);
            aL0 = *(const uint4*)(aLp + k0);
            aL1 = *(const uint4*)(aLp + k0 + 4);
            bHr = *(const uint4*)(wHp + (size_t)(k0 + bp) * 1024);
            bLr = *(const uint4*)(wLp + (size_t)(k0 + bp) * 1024);
        }

        // compute: 2 k16 steps
#pragma unroll
        for (int ks = 0; ks < 2; ks++) {
            int kp = ks * 8;
            unsigned afH[2][4], afL[2][4], bfH[4][2], bfL[4][2];
#pragma unroll
            for (int mi = 0; mi < 2; mi++) {
                int r = wm + mi * 16 + g;
                afH[mi][0] = AsH[r * APITCH + kp + tig];
                afH[mi][1] = AsH[(r + 8) * APITCH + kp + tig];
                afH[mi][2] = AsH[r * APITCH + kp + tig + 4];
                afH[mi][3] = AsH[(r + 8) * APITCH + kp + tig + 4];
                afL[mi][0] = AsL[r * APITCH + kp + tig];
                afL[mi][1] = AsL[(r + 8) * APITCH + kp + tig];
                afL[mi][2] = AsL[r * APITCH + kp + tig + 4];
                afL[mi][3] = AsL[(r + 8) * APITCH + kp + tig + 4];
            }
#pragma unroll
            for (int ni = 0; ni < 4; ni++) {
                int c = wn + ni * 8 + g;
                bfH[ni][0] = BsH[(kp + tig) * BPITCH + c];
                bfH[ni][1] = BsH[(kp + tig + 4) * BPITCH + c];
                bfL[ni][0] = BsL[(kp + tig) * BPITCH + c];
                bfL[ni][1] = BsL[(kp + tig + 4) * BPITCH + c];
            }
#pragma unroll
            for (int mi = 0; mi < 2; mi++)
#pragma unroll
                for (int ni = 0; ni < 4; ni++)
                    mma3(acc[mi][ni], afH[mi], afL[mi], bfH[ni][0], bfH[ni][1],
                         bfL[ni][0], bfL[ni][1]);
        }
        __syncthreads();
    }

    // epilogue
    if (mode == 0) {
#pragma unroll
        for (int mi = 0; mi < 2; mi++)
#pragma unroll
            for (int ni = 0; ni < 4; ni++) {
                int r0 = by * 128 + wm + mi * 16 + g;
                int c0 = bx * 64 + wn + ni * 8 + tig * 2;
                *(float2*)(Copt + (size_t)r0 * 1024 + c0) =
                    make_float2(acc[mi][ni][0], acc[mi][ni][1]);
                *(float2*)(Copt + (size_t)(r0 + 8) * 1024 + c0) =
                    make_float2(acc[mi][ni][2], acc[mi][ni][3]);
            }
    } else {
        float* dst = (z == 0) ? g_q : (z == 1) ? g_k : g_v;
#pragma unroll
        for (int mi = 0; mi < 2; mi++)
#pragma unroll
            for (int ni = 0; ni < 4; ni++) {
                int r0 = by * 128 + wm + mi * 16 + g;
                int c0 = bx * 64 + wn + ni * 8 + tig * 2;
                int h = c0 >> 6, d = c0 & 63;
                {
                    int b = r0 >> 11, s = r0 & 2047;
                    *(float2*)(dst + (size_t)((b * H_ + h) * S_ + s) * DK + d) =
                        make_float2(acc[mi][ni][0], acc[mi][ni][1]);
                }
                {
                    int r1 = r0 + 8;
                    int b = r1 >> 11, s = r1 & 2047;
                    *(float2*)(dst + (size_t)((b * H_ + h) * S_ + s) * DK + d) =
                        make_float2(acc[mi][ni][2], acc[mi][ni][3]);
                }
            }
    }
}

// ---------------- 3xBF16 flash attention, 128x64 tiles, 8 warps (R10) -------
#define QP 36
#define KP 36
#define VP 72
#define PP 36
#define FLASH_SMEM ((2 * 128 * QP + 2 * 64 * KP + 2 * 32 * VP + \
                     2 * 128 * PP + 192) * 4)

__global__ __launch_bounds__(256) void flash_bf16x3() {
    extern __shared__ unsigned smu[];
    unsigned* QsH = smu;
    unsigned* QsL = QsH + 128 * QP;
    unsigned* KsH = QsL + 128 * QP;
    unsigned* KsL = KsH + 64 * KP;
    unsigned* VsH = KsL + 64 * KP;
    unsigned* VsL = VsH + 32 * VP;
    unsigned* PsH = VsL + 32 * VP;
    unsigned* PsL = PsH + 128 * PP;
    float* sB = (float*)(PsL + 128 * PP);

    int qb = blockIdx.x, h = blockIdx.y, b = blockIdx.z;
    int tid  = threadIdx.x;
    int warp = tid >> 5, lane = tid & 31;
    int g = lane >> 2, tig = lane & 3;

    const float* Qg = g_q + ((size_t)(b * H_ + h) * S_ + qb * 128) * DK;
    const float* Kg = g_k + (size_t)(b * H_ + h) * S_ * DK;
    const float* Vg = g_v + (size_t)(b * H_ + h) * S_ * DK;

#pragma unroll
    for (int i = 0; i < 8; i++) {
        int ch = tid + i * 256;
        int r = ch >> 4, cq = ch & 15;
        float4 v = *(const float4*)(Qg + (size_t)r * DK + cq * 4);
        uint2 hh, ll;
        split2(v.x, v.y, hh.x, ll.x);
        split2(v.z, v.w, hh.y, ll.y);
        *(uint2*)&QsH[r * QP + cq * 2] = hh;
        *(uint2*)&QsL[r * QP + cq * 2] = ll;
    }

    float oacc[8][4];
#pragma unroll
    for (int ni = 0; ni < 8; ni++)
#pragma unroll
        for (int c = 0; c < 4; c++) oacc[ni][c] = 0.0f;
    float m_i[2] = {-1e30f, -1e30f}, l_i[2] = {0.0f, 0.0f};

    for (int kb = 0; kb < S_ / 64; kb++) {
#pragma unroll
        for (int i = 0; i < 4; i++) {
            int ch = tid + i * 256;
            int r = ch >> 4, cq = ch & 15;
            float4 kv = *(const float4*)(Kg + (size_t)(kb * 64 + r) * DK + cq * 4);
            uint2 hh, ll;
            split2(kv.x, kv.y, hh.x, ll.x);
            split2(kv.z, kv.w, hh.y, ll.y);
            *(uint2*)&KsH[r * KP + cq * 2] = hh;
            *(uint2*)&KsL[r * KP + cq * 2] = ll;
        }
#pragma unroll
        for (int i = 0; i < 2; i++) {
            int u = tid + i * 256;
            int p = u >> 4, cq = u & 15;
            float4 va = *(const float4*)(Vg + (size_t)(kb * 64 + 2 * p) * DK + cq * 4);
            float4 vb = *(const float4*)(Vg + (size_t)(kb * 64 + 2 * p + 1) * DK + cq * 4);
            uint4 hh, ll;
            split2(va.x, vb.x, hh.x, ll.x);
            split2(va.y, vb.y, hh.y, ll.y);
            split2(va.z, vb.z, hh.z, ll.z);
            split2(va.w, vb.w, hh.w, ll.w);
            *(uint4*)&VsH[p * VP + cq * 4] = hh;
            *(uint4*)&VsL[p * VP + cq * 4] = ll;
        }
        if (tid < 191)
            sB[tid] = g_bias[h * NREL + (kb * 64 - qb * 128) - 127 + 2047 + tid];
        __syncthreads();

        float sacc[8][4];
#pragma unroll
        for (int ni = 0; ni < 8; ni++)
#pragma unroll
            for (int c = 0; c < 4; c++) sacc[ni][c] = 0.0f;

#pragma unroll
        for (int ks = 0; ks < 4; ks++) {
            int kp = ks * 8;
            int rq = warp * 16 + g;
            unsigned aH[4], aL[4];
            aH[0] = QsH[rq * QP + kp + tig];
            aH[1] = QsH[(rq + 8) * QP + kp + tig];
            aH[2] = QsH[rq * QP + kp + tig + 4];
            aH[3] = QsH[(rq + 8) * QP + kp + tig + 4];
            aL[0] = QsL[rq * QP + kp + tig];
            aL[1] = QsL[(rq + 8) * QP + kp + tig];
            aL[2] = QsL[rq * QP + kp + tig + 4];
            aL[3] = QsL[(rq + 8) * QP + kp + tig + 4];
#pragma unroll
            for (int ni = 0; ni < 8; ni++) {
                int rk = ni * 8 + g;
                unsigned bH0 = KsH[rk * KP + kp + tig];
                unsigned bH1 = KsH[rk * KP + kp + tig + 4];
                unsigned bL0 = KsL[rk * KP + kp + tig];
                unsigned bL1 = KsL[rk * KP + kp + tig + 4];
                mma3(sacc[ni], aH, aL, bH0, bH1, bL0, bL1);
            }
        }

#pragma unroll
        for (int rh = 0; rh < 2; rh++) {
            int qr = warp * 16 + g + 8 * rh;
            float rm = -1e30f;
#pragma unroll
            for (int ni = 0; ni < 8; ni++) {
                int kc = ni * 8 + tig * 2;
                sacc[ni][2 * rh]     += sB[kc - qr + 127];
                sacc[ni][2 * rh + 1] += sB[kc + 1 - qr + 127];
                rm = fmaxf(rm, fmaxf(sacc[ni][2 * rh], sacc[ni][2 * rh + 1]));
            }
            rm = fmaxf(rm, __shfl_xor_sync(0xffffffffu, rm, 1));
            rm = fmaxf(rm, __shfl_xor_sync(0xffffffffu, rm, 2));
            float mn   = fmaxf(m_i[rh], rm);
            float corr = __expf(m_i[rh] - mn);
            float rs = 0.0f;
#pragma unroll
            for (int ni = 0; ni < 8; ni++) {
                float p0 = __expf(sacc[ni][2 * rh] - mn);
                float p1 = __expf(sacc[ni][2 * rh + 1] - mn);
                rs += p0 + p1;
                unsigned ph, pl;
                split2(p0, p1, ph, pl);
                PsH[qr * PP + ni * 4 + tig] = ph;
                PsL[qr * PP + ni * 4 + tig] = pl;
                oacc[ni][2 * rh]     *= corr;
                oacc[ni][2 * rh + 1] *= corr;
            }
            rs += __shfl_xor_sync(0xffffffffu, rs, 1);
            rs += __shfl_xor_sync(0xffffffffu, rs, 2);
            l_i[rh] = l_i[rh] * corr + rs;
            m_i[rh] = mn;
        }
        __syncwarp();

#pragma unroll
        for (int ks = 0; ks < 4; ks++) {
            int kp = ks * 8;
            int pr = warp * 16 + g;
            unsigned aH[4], aL[4];
            aH[0] = PsH[pr * PP + kp + tig];
            aH[1] = PsH[(pr + 8) * PP + kp + tig];
            aH[2] = PsH[pr * PP + kp + tig + 4];
            aH[3] = PsH[(pr + 8) * PP + kp + tig + 4];
            aL[0] = PsL[pr * PP + kp + tig];
            aL[1] = PsL[(pr + 8) * PP + kp + tig];
            aL[2] = PsL[pr * PP + kp + tig + 4];
            aL[3] = PsL[(pr + 8) * PP + kp + tig + 4];
#pragma unroll
            for (int ni = 0; ni < 8; ni++) {
                int d = ni * 8 + g;
                unsigned bH0 = VsH[(kp + tig) * VP + d];
                unsigned bH1 = VsH[(kp + tig + 4) * VP + d];
                unsigned bL0 = VsL[(kp + tig) * VP + d];
                unsigned bL1 = VsL[(kp + tig + 4) * VP + d];
                mma3(oacc[ni], aH, aL, bH0, bH1, bL0, bL1);
            }
        }
        __syncthreads();
    }

    float inv0 = 1.0f / l_i[0], inv1 = 1.0f / l_i[1];
#pragma unroll
    for (int ni = 0; ni < 8; ni++) {
        int q0 = qb * 128 + warp * 16 + g;
        int d0 = ni * 8 + tig * 2;
        *(float2*)(g_ctx + ((size_t)b * S_ + q0) * INNER_ + h * DK + d0) =
            make_float2(oacc[ni][0] * inv0, oacc[ni][1] * inv0);
        *(float2*)(g_ctx + ((size_t)b * S_ + q0 + 8) * INNER_ + h * DK + d0) =
            make_float2(oacc[ni][2] * inv1, oacc[ni][3] * inv1);
    }
}

// ---------------- launch ----------------
extern "C" void kernel_launch(void* const* d_in, const int* in_sizes, int n_in,
                              void* d_out, int out_size) {
    const float* X     = (const float*)d_in[0];
    const float* wq    = (const float*)d_in[1];
    const float* wk    = (const float*)d_in[2];
    const float* wv    = (const float*)d_in[3];
    const float* wo    = (const float*)d_in[4];
    const float* table = (const float*)d_in[5];
    float* out = (float*)d_out;

    cudaFuncSetAttribute(flash_bf16x3,
                         cudaFuncAttributeMaxDynamicSharedMemorySize, FLASH_SMEM);

    // 1. bias table + one-time splits
    bias_kernel<<<(H_ * NREL + 255) / 256, 256>>>(table);
    prep_x<<<4096 * 512 / 256, 256>>>(X);
    dim3 gw(512 * 1024 / 256, 4);
    prep_w<<<gw, 256>>>(wq, wk, wv, wo);

    // 2. fused Q/K/V projections (2 CTAs/SM)
    dim3 gq(INNER_ / 64, (B_ * S_) / 128, 3);
    gemm_occ<<<gq, 256>>>(nullptr, 1);

    // 3. flash attention (identical to the 744us R10 version)
    dim3 ga(S_ / 128, H_, B_);
    flash_bf16x3<<<ga, 256, FLASH_SMEM>>>();

    // 4. split ctx, then output projection
    prep_c<<<4096 * 512 / 256, 256>>>();
    dim3 go(DM / 64, (B_ * S_) / 128, 1);
    gemm_occ<<<go, 256>>>(out, 0);
}